// round 17
// baseline (speedup 1.0000x reference)
#include <cuda_runtime.h>
#include <cstdint>

#define TT 2048
#define BB 128
#define HH 200
#define KS 20     // k-span per chunk (10 chunks x 20 = 200)
#define NKC 10    // k-chunks
#define NJO 25    // j-octets (8 j each)
// Block 256 (8 warps), grid 64: ONE CTA runs TWO batch rows (A, B).
// compute threads tid<250: (kc, jo) own 8 W-rows x 20-k ONCE, run 2 acc sets.
// Phase B: tid<200 finish neuron tid for both batches; warp 7 runs both heads.

typedef unsigned long long ull;

__device__ __forceinline__ void fma2(ull& acc, ull a, ull b) {
    asm("fma.rn.f32x2 %0, %1, %2, %0;" : "+l"(acc) : "l"(a), "l"(b));
}
__device__ __forceinline__ void unpack2(ull v, float& lo, float& hi) {
    asm("mov.b64 {%0,%1}, %2;" : "=f"(lo), "=f"(hi) : "l"(v));
}
__device__ __forceinline__ float tanh_hw(float x) {
    float r; asm("tanh.approx.f32 %0, %1;" : "=f"(r) : "f"(x));
    return r;
}

__global__ void __launch_bounds__(256, 1) rnn_kernel(
    const float* __restrict__ x,     // [T, B, 2]
    const float* __restrict__ Wih,   // [H, 2]
    const float* __restrict__ Whh,   // [H, H]
    const float* __restrict__ bih,   // [H]
    const float* __restrict__ bhh,   // [H]
    const float* __restrict__ Wout,  // [1, H]
    const float* __restrict__ bOut,  // [1]
    float* __restrict__ out)         // [T, B, 1]
{
    __shared__ __align__(16) float2 xsmA[TT];          // 16 KB batch A inputs
    __shared__ __align__(16) float2 xsmB[TT];          // 16 KB batch B inputs
    __shared__ __align__(16) float  hsmA[2][HH];       // A hidden, double-buffered
    __shared__ __align__(16) float  hsmB[2][HH];       // B hidden, double-buffered
    __shared__ __align__(16) float  partA[NKC * HH];   // A partials [kc*200 + j]
    __shared__ __align__(16) float  partB[NKC * HH];   // B partials
    __shared__ __align__(16) float  wosm[HH];          // Wout staged

    const int tid = threadIdx.x;
    const int b0  = 2 * blockIdx.x;
    const int b1  = b0 + 1;
    const int kc  = tid / NJO;        // 0..9 for compute threads
    const int jo  = tid - kc * NJO;   // 0..24
    const bool compute = (tid < 250);
    const int lane = tid & 31;
    const bool headw = (tid >= 224);  // warp 7: head duty in phase B

    // Preload both input sequences
    for (int i = tid; i < TT; i += 256) {
        xsmA[i] = *(const float2*)(x + ((size_t)i * BB + b0) * 2);
        xsmB[i] = *(const float2*)(x + ((size_t)i * BB + b1) * 2);
    }
    if (tid < HH) wosm[tid] = Wout[tid];

    // W registers: 8 rows (j = 8jo+r), k-chunk [20kc, +20) as 10 u64 each.
    // Held ONCE, used for both batches.
    ull wr[8][10];
    if (compute) {
#pragma unroll
        for (int r = 0; r < 8; r++) {
            const ull* wrow = (const ull*)(Whh + (size_t)(8 * jo + r) * HH + KS * kc);
#pragma unroll
            for (int i = 0; i < 10; i++) wr[r][i] = wrow[i];
        }
    }

    // Epilogue constants (threads 0..199, keyed by j = tid)
    float wih0 = 0.f, wih1 = 0.f, bias = 0.f;
    if (tid < HH) {
        wih0 = Wih[2 * tid];
        wih1 = Wih[2 * tid + 1];
        bias = bih[tid] + bhh[tid];
    }
    const float bo = bOut[0];

    // h_0 = 0 in both buffers, both batches
    if (tid < 2 * HH) {
        ((float*)hsmA)[tid] = 0.0f;
        ((float*)hsmB)[tid] = 0.0f;
    }
    __syncthreads();

    // iter t: hsm*[rp] = h_{t-1}; phase B writes hs[t] into hsm*[rp^1];
    // warp 7 emits out[t-1] for both batches during phase B.
    auto step = [&](int t, int rp) {
        // ---- Phase A: 8-row x 20-k partials for BOTH batches (16 ILP chains)
        if (compute) {
            const ulonglong2* hpA = (const ulonglong2*)(&hsmA[rp][KS * kc]);
            const ulonglong2* hpB = (const ulonglong2*)(&hsmB[rp][KS * kc]);
            ull aA[8] = {0,0,0,0,0,0,0,0};
            ull aB[8] = {0,0,0,0,0,0,0,0};
#pragma unroll
            for (int i = 0; i < 5; i++) {
                ulonglong2 hvA = hpA[i];           // LDS.128, reused 8x
                ulonglong2 hvB = hpB[i];
#pragma unroll
                for (int r = 0; r < 8; r++) {
                    fma2(aA[r], hvA.x, wr[r][2 * i]);
                    fma2(aA[r], hvA.y, wr[r][2 * i + 1]);
                    fma2(aB[r], hvB.x, wr[r][2 * i]);
                    fma2(aB[r], hvB.y, wr[r][2 * i + 1]);
                }
            }
            float4 pA0, pA1, pB0, pB1;
            { float lo, hi; unpack2(aA[0], lo, hi); pA0.x = lo + hi; }
            { float lo, hi; unpack2(aA[1], lo, hi); pA0.y = lo + hi; }
            { float lo, hi; unpack2(aA[2], lo, hi); pA0.z = lo + hi; }
            { float lo, hi; unpack2(aA[3], lo, hi); pA0.w = lo + hi; }
            { float lo, hi; unpack2(aA[4], lo, hi); pA1.x = lo + hi; }
            { float lo, hi; unpack2(aA[5], lo, hi); pA1.y = lo + hi; }
            { float lo, hi; unpack2(aA[6], lo, hi); pA1.z = lo + hi; }
            { float lo, hi; unpack2(aA[7], lo, hi); pA1.w = lo + hi; }
            { float lo, hi; unpack2(aB[0], lo, hi); pB0.x = lo + hi; }
            { float lo, hi; unpack2(aB[1], lo, hi); pB0.y = lo + hi; }
            { float lo, hi; unpack2(aB[2], lo, hi); pB0.z = lo + hi; }
            { float lo, hi; unpack2(aB[3], lo, hi); pB0.w = lo + hi; }
            { float lo, hi; unpack2(aB[4], lo, hi); pB1.x = lo + hi; }
            { float lo, hi; unpack2(aB[5], lo, hi); pB1.y = lo + hi; }
            { float lo, hi; unpack2(aB[6], lo, hi); pB1.z = lo + hi; }
            { float lo, hi; unpack2(aB[7], lo, hi); pB1.w = lo + hi; }
            const int off = 200 * kc + 8 * jo;     // 16B-aligned
            *(float4*)(&partA[off])     = pA0;
            *(float4*)(&partA[off + 4]) = pA1;
            *(float4*)(&partB[off])     = pB0;
            *(float4*)(&partB[off + 4]) = pB1;
        }
        __syncthreads();

        // ---- Phase B: reduce + tanh + publish for both batches (tid<200);
        //               warp 7: heads(h_{t-1}) -> out[t-1] x2
        if (tid < HH) {
            float sA = 0.0f, sB = 0.0f;
#pragma unroll
            for (int c = 0; c < NKC; c++) {
                sA += partA[200 * c + tid];
                sB += partB[200 * c + tid];
            }
            float2 xA = xsmA[t];
            float2 xB = xsmB[t];
            float preA = fmaf(xA.x, wih0, fmaf(xA.y, wih1, sA + bias));
            float preB = fmaf(xB.x, wih0, fmaf(xB.y, wih1, sB + bias));
            hsmA[rp ^ 1][tid] = tanh_hw(preA);
            hsmB[rp ^ 1][tid] = tanh_hw(preB);
        } else if (headw && t > 0) {
            const float* hvA = hsmA[rp];
            const float* hvB = hsmB[rp];
            float accA = 0.0f, accB = 0.0f;
#pragma unroll
            for (int i = 0; i < 7; i++) {
                int idx = lane + 32 * i;
                if (idx < HH) {
                    accA = fmaf(hvA[idx], wosm[idx], accA);
                    accB = fmaf(hvB[idx], wosm[idx], accB);
                }
            }
#pragma unroll
            for (int off = 16; off; off >>= 1) {
                accA += __shfl_xor_sync(0xFFFFFFFFu, accA, off);
                accB += __shfl_xor_sync(0xFFFFFFFFu, accB, off);
            }
            if (lane == 0) {
                out[(size_t)(t - 1) * BB + b0] = accA + bo;
                out[(size_t)(t - 1) * BB + b1] = accB + bo;
            }
        }
        __syncthreads();
    };

#pragma unroll 1
    for (int t = 0; t < TT; t += 2) {
        step(t, 0);
        step(t + 1, 1);
    }

    // Final outputs: hs[TT-1] ended in hsm*[0]
    if (headw) {
        const float* hvA = hsmA[0];
        const float* hvB = hsmB[0];
        float accA = 0.0f, accB = 0.0f;
#pragma unroll
        for (int i = 0; i < 7; i++) {
            int idx = lane + 32 * i;
            if (idx < HH) {
                accA = fmaf(hvA[idx], wosm[idx], accA);
                accB = fmaf(hvB[idx], wosm[idx], accB);
            }
        }
#pragma unroll
        for (int off = 16; off; off >>= 1) {
            accA += __shfl_xor_sync(0xFFFFFFFFu, accA, off);
            accB += __shfl_xor_sync(0xFFFFFFFFu, accB, off);
        }
        if (lane == 0) {
            out[(size_t)(TT - 1) * BB + b0] = accA + bo;
            out[(size_t)(TT - 1) * BB + b1] = accB + bo;
        }
    }
}

extern "C" void kernel_launch(void* const* d_in, const int* in_sizes, int n_in,
                              void* d_out, int out_size) {
    const float* input_seq = (const float*)d_in[0];  // [T,B,2]
    const float* W_ih      = (const float*)d_in[1];  // [H,2]
    const float* W_hh      = (const float*)d_in[2];  // [H,H]
    const float* b_ih      = (const float*)d_in[3];  // [H]
    const float* b_hh      = (const float*)d_in[4];  // [H]
    const float* W_out     = (const float*)d_in[5];  // [1,H]
    const float* b_out     = (const float*)d_in[6];  // [1]
    float* out = (float*)d_out;                      // [T,B,1]

    rnn_kernel<<<BB / 2, 256>>>(input_seq, W_ih, W_hh, b_ih, b_hh,
                                W_out, b_out, out);
}